// round 5
// baseline (speedup 1.0000x reference)
#include <cuda_runtime.h>
#include <math.h>

#define BB 64
#define TT 2048
#define DD 256
#define BT (BB*TT)
#define EPSF 1e-7f

#define MTILE 64
#define KC 32
#define TSPLIT 16
#define TCHUNK (TT/TSPLIT)   // 128

// Scratch (no allocations allowed in kernel_launch)
__device__ float g_score[BT];            // exp(e)*mask
__device__ float g_denom[BB];            // sum over T + EPS
__device__ float g_partial[BB*TSPLIT*DD];

// ---------------------------------------------------------------------------
// Kernel 1: e[row] = sum_n tanh( (x[row,:] @ W)[n] + b[n] ) * uw[n]
//           g_score[row] = exp(e) * mask[row]
// Tiled GEMM: block tile 64 rows x 256 cols, K in chunks of 32.
// 256 threads: tx = tid&15 (n-groups, n = tx + 16j), ty = tid>>4 (m-groups, m = 4*ty+i)
// Register tile 4x16 accumulators per thread.
// ---------------------------------------------------------------------------
__global__ __launch_bounds__(256, 2)
void score_kernel(const float* __restrict__ x,
                  const float* __restrict__ W,
                  const float* __restrict__ bias,
                  const float* __restrict__ uw,
                  const int*   __restrict__ mask)
{
    __shared__ float xs[MTILE][KC + 1];   // +1 pad: conflict-free broadcast reads
    __shared__ float ws[KC][DD];

    const int tid = threadIdx.x;
    const int tx  = tid & 15;
    const int ty  = tid >> 4;
    const long rowbase = (long)blockIdx.x * MTILE;

    float acc[4][16];
#pragma unroll
    for (int i = 0; i < 4; i++)
#pragma unroll
        for (int j = 0; j < 16; j++) acc[i][j] = 0.0f;

    for (int kt = 0; kt < DD; kt += KC) {
        // Load x tile: 64x32 = 2048 floats, 8 per thread (coalesced 32-wide rows)
#pragma unroll
        for (int i = 0; i < 8; i++) {
            int idx = tid + i * 256;
            int m = idx >> 5, k = idx & 31;
            xs[m][k] = x[(rowbase + m) * DD + kt + k];
        }
        // Load W tile: 32x256 = 8192 floats, 32 per thread (fully coalesced)
#pragma unroll
        for (int i = 0; i < 32; i++) {
            int idx = tid + i * 256;
            int k = idx >> 8, n = idx & 255;
            ws[k][n] = W[(kt + k) * DD + n];
        }
        __syncthreads();

#pragma unroll
        for (int k = 0; k < KC; k++) {
            float av[4], bw[16];
#pragma unroll
            for (int i = 0; i < 4; i++) av[i] = xs[ty * 4 + i][k];   // broadcast within warp
#pragma unroll
            for (int j = 0; j < 16; j++) bw[j] = ws[k][tx + 16 * j]; // lanes 0..15 consecutive, half-warps broadcast
#pragma unroll
            for (int i = 0; i < 4; i++)
#pragma unroll
                for (int j = 0; j < 16; j++)
                    acc[i][j] = fmaf(av[i], bw[j], acc[i][j]);
        }
        __syncthreads();
    }

    // Epilogue: tanh(+bias) * uw, reduce the 256 n's of each row.
    // Row m's n-values live on the 16 lanes sharing ty (16 j's per lane).
#pragma unroll
    for (int i = 0; i < 4; i++) {
        float s = 0.0f;
#pragma unroll
        for (int j = 0; j < 16; j++) {
            int n = tx + 16 * j;
            s += tanhf(acc[i][j] + bias[n]) * uw[n];
        }
        // reduce across the 16-lane group (tx dimension)
#pragma unroll
        for (int off = 8; off > 0; off >>= 1)
            s += __shfl_xor_sync(0xffffffffu, s, off, 16);
        if (tx == 0) {
            long row = rowbase + ty * 4 + i;
            g_score[row] = expf(s) * (float)mask[row];
        }
    }
}

// ---------------------------------------------------------------------------
// Kernel 2: per-batch denominator
// ---------------------------------------------------------------------------
__global__ void denom_kernel()
{
    __shared__ float red[256];
    const int b = blockIdx.x, tid = threadIdx.x;
    float s = 0.0f;
    for (int t = tid; t < TT; t += 256) s += g_score[(long)b * TT + t];
    red[tid] = s;
    __syncthreads();
    for (int o = 128; o > 0; o >>= 1) {
        if (tid < o) red[tid] += red[tid + o];
        __syncthreads();
    }
    if (tid == 0) g_denom[b] = red[0] + EPSF;
}

// ---------------------------------------------------------------------------
// Kernel 3: split-T weighted sum (deterministic partials, no atomics)
// block (b, ts): 256 threads = d; each covers 128 t's.
// ---------------------------------------------------------------------------
__global__ __launch_bounds__(256)
void weighted_kernel(const float* __restrict__ x)
{
    const int b = blockIdx.x, ts = blockIdx.y, d = threadIdx.x;
    __shared__ float sc[TCHUNK];
    const int t0 = ts * TCHUNK;
    if (d < TCHUNK) sc[d] = g_score[(long)b * TT + t0 + d];
    __syncthreads();

    float acc = 0.0f;
    const float* xp = x + ((long)b * TT + t0) * DD + d;
#pragma unroll 4
    for (int t = 0; t < TCHUNK; t++)
        acc = fmaf(xp[(long)t * DD], sc[t], acc);
    g_partial[((long)b * TSPLIT + ts) * DD + d] = acc;
}

// ---------------------------------------------------------------------------
// Kernel 4: finalize
// ---------------------------------------------------------------------------
__global__ void finalize_kernel(float* __restrict__ out)
{
    const int b = blockIdx.x, d = threadIdx.x;
    float s = 0.0f;
#pragma unroll
    for (int ts = 0; ts < TSPLIT; ts++)
        s += g_partial[((long)b * TSPLIT + ts) * DD + d];
    out[b * DD + d] = s / g_denom[b];
}

// ---------------------------------------------------------------------------
extern "C" void kernel_launch(void* const* d_in, const int* in_sizes, int n_in,
                              void* d_out, int out_size)
{
    const float* x    = (const float*)d_in[0];  // [64,2048,256]
    const float* W    = (const float*)d_in[1];  // [256,256]
    const float* bias = (const float*)d_in[2];  // [256]
    const float* uw   = (const float*)d_in[3];  // [256]
    const int*   mask = (const int*)  d_in[4];  // [64,2048]
    float* out = (float*)d_out;                 // [64,256]

    score_kernel<<<BT / MTILE, 256>>>(x, W, bias, uw, mask);
    denom_kernel<<<BB, 256>>>();
    weighted_kernel<<<dim3(BB, TSPLIT), 256>>>(x);
    finalize_kernel<<<BB, DD>>>(out);
}

// round 8
// speedup vs baseline: 2.5001x; 2.5001x over previous
#include <cuda_runtime.h>
#include <cuda_bf16.h>
#include <cstdint>
#include <math.h>

#define BB 64
#define TT 2048
#define DD 256
#define BT (BB*TT)
#define EPSF 1e-7f

#define MT 64             // rows per CTA
#define KC 64             // K chunk
#define SK 72             // padded smem stride (elems): 144B rows -> conflict-free frags
#define NCHUNK (DD/KC)    // 4
#define TSPLIT 16
#define TCHUNK (TT/TSPLIT)

// ---------------- scratch ----------------
__device__ __nv_bfloat16 g_Whi[DD*DD];   // W^T hi, [n][k]
__device__ __nv_bfloat16 g_Wlo[DD*DD];   // W^T lo, [n][k]
__device__ float g_score[BT];
__device__ float g_denom[BB];
__device__ float g_partial[BB*TSPLIT*DD];

// ---------------- smem layout (bytes) ----------------
#define OFF_XHI  0
#define OFF_XLO  (OFF_XHI + MT*SK*2)        //  9216
#define OFF_WHI  (OFF_XLO + MT*SK*2)        // 18432
#define OFF_WLO  (OFF_WHI + DD*SK*2)        // 55296
#define OFF_RED  (OFF_WLO + DD*SK*2)        // 92160 : red[64][4] f32
#define OFF_BIAS (OFF_RED + 64*4*4)         // 93184
#define OFF_UW   (OFF_BIAS + 1024)          // 94208
#define SMEM_BYTES (OFF_UW + 1024)          // 95232

// ---------------- helpers ----------------
__device__ __forceinline__ void mma16816(float* c, const uint32_t* a, const uint32_t* b) {
    asm volatile(
        "mma.sync.aligned.m16n8k16.row.col.f32.bf16.bf16.f32 "
        "{%0,%1,%2,%3}, {%4,%5,%6,%7}, {%8,%9}, {%0,%1,%2,%3};"
        : "+f"(c[0]), "+f"(c[1]), "+f"(c[2]), "+f"(c[3])
        : "r"(a[0]), "r"(a[1]), "r"(a[2]), "r"(a[3]), "r"(b[0]), "r"(b[1]));
}
__device__ __forceinline__ float tanh_approx(float x) {
    float y;
    asm("tanh.approx.f32 %0, %1;" : "=f"(y) : "f"(x));
    return y;
}
__device__ __forceinline__ uint32_t lds32(const char* smem, int elem) {
    return *reinterpret_cast<const uint32_t*>(smem + (size_t)elem * 2);
}
// split two fp32 into packed bf16x2 hi-word / lo-word
__device__ __forceinline__ void split2(float a, float b, uint32_t& hi, uint32_t& lo) {
    __nv_bfloat16 ha = __float2bfloat16(a), hb = __float2bfloat16(b);
    float la = a - __bfloat162float(ha);
    float lb = b - __bfloat162float(hb);
    __nv_bfloat162 H; H.x = ha; H.y = hb;
    __nv_bfloat162 L; L.x = __float2bfloat16(la); L.y = __float2bfloat16(lb);
    hi = *reinterpret_cast<uint32_t*>(&H);
    lo = *reinterpret_cast<uint32_t*>(&L);
}

// ---------------------------------------------------------------------------
// Kernel 0: pre-split & transpose W -> g_Whi/g_Wlo as [n][k]
// ---------------------------------------------------------------------------
__global__ void prep_w(const float* __restrict__ W) {
    int n = blockIdx.x, k = threadIdx.x;
    float w = W[k * DD + n];
    __nv_bfloat16 h = __float2bfloat16(w);
    g_Whi[n * DD + k] = h;
    g_Wlo[n * DD + k] = __float2bfloat16(w - __bfloat162float(h));
}

// ---------------------------------------------------------------------------
// Kernel 1: split-bf16 mma.sync GEMM + fused tanh/uw/exp epilogue
// 8 warps: wm = wid&1 (2 in M), wn = wid>>1 (4 in N). Warp tile 32x64.
// ---------------------------------------------------------------------------
__global__ __launch_bounds__(256, 2)
void score_mma_kernel(const float* __restrict__ x,
                      const float* __restrict__ bias,
                      const float* __restrict__ uw,
                      const int*   __restrict__ mask)
{
    extern __shared__ char smem[];
    const int tid = threadIdx.x;
    const int wid = tid >> 5, lane = tid & 31;
    const int wm = wid & 1, wn = wid >> 1;
    const int g = lane >> 2, t = lane & 3;
    const long rowbase = (long)blockIdx.x * MT;

    // cache bias/uw in smem
    *(float*)(smem + OFF_BIAS + tid * 4) = bias[tid];
    *(float*)(smem + OFF_UW   + tid * 4) = uw[tid];

    float acc[2][8][4];
#pragma unroll
    for (int mt = 0; mt < 2; mt++)
#pragma unroll
        for (int nt = 0; nt < 8; nt++)
#pragma unroll
            for (int i = 0; i < 4; i++) acc[mt][nt][i] = 0.0f;

    const int xrow = tid >> 2;          // 0..63
    const int xcb  = (tid & 3) * 16;    // col base within chunk

    for (int c = 0; c < NCHUNK; c++) {
        const int kt = c * KC;

        // --- stage x (fp32 -> split bf16), rows 64 x cols 64 ---
        const float4* xp = (const float4*)(x + (rowbase + xrow) * DD + kt + xcb);
#pragma unroll
        for (int q = 0; q < 4; q++) {
            float4 v = xp[q];
            uint32_t h01, l01, h23, l23;
            split2(v.x, v.y, h01, l01);
            split2(v.z, v.w, h23, l23);
            int e = xrow * SK + xcb + q * 4;             // byte = 2e, 8B aligned
            *(uint2*)(smem + OFF_XHI + (size_t)e * 2) = make_uint2(h01, h23);
            *(uint2*)(smem + OFF_XLO + (size_t)e * 2) = make_uint2(l01, l23);
        }
        // --- stage W^T tiles (bf16), n = tid, 64 k each ---
        {
            const uint4* whp = (const uint4*)(g_Whi + tid * DD + kt);
            const uint4* wlp = (const uint4*)(g_Wlo + tid * DD + kt);
#pragma unroll
            for (int q = 0; q < 8; q++) {
                int e = tid * SK + q * 8;                // byte = 2e, 16B aligned
                *(uint4*)(smem + OFF_WHI + (size_t)e * 2) = whp[q];
                *(uint4*)(smem + OFF_WLO + (size_t)e * 2) = wlp[q];
            }
        }
        __syncthreads();

        // --- 4 k16-steps per chunk ---
#pragma unroll
        for (int ks = 0; ks < 4; ks++) {
            const int kb = ks * 16;
            // A fragments (hi & lo) for both m-tiles
            uint32_t ahi[2][4], alo[2][4];
#pragma unroll
            for (int mt = 0; mt < 2; mt++) {
                int r0 = (wm * 32 + mt * 16 + g) * SK + kb + 2 * t;
                int r1 = r0 + 8 * SK;
                ahi[mt][0] = lds32(smem + OFF_XHI, r0);
                ahi[mt][1] = lds32(smem + OFF_XHI, r1);
                ahi[mt][2] = lds32(smem + OFF_XHI, r0 + 8);
                ahi[mt][3] = lds32(smem + OFF_XHI, r1 + 8);
                alo[mt][0] = lds32(smem + OFF_XLO, r0);
                alo[mt][1] = lds32(smem + OFF_XLO, r1);
                alo[mt][2] = lds32(smem + OFF_XLO, r0 + 8);
                alo[mt][3] = lds32(smem + OFF_XLO, r1 + 8);
            }
#pragma unroll
            for (int nt = 0; nt < 8; nt++) {
                int ne = (wn * 64 + nt * 8 + g) * SK + kb + 2 * t;
                uint32_t bhi[2], blo[2];
                bhi[0] = lds32(smem + OFF_WHI, ne);
                bhi[1] = lds32(smem + OFF_WHI, ne + 8);
                blo[0] = lds32(smem + OFF_WLO, ne);
                blo[1] = lds32(smem + OFF_WLO, ne + 8);
#pragma unroll
                for (int mt = 0; mt < 2; mt++) {
                    mma16816(acc[mt][nt], ahi[mt], bhi);   // hi*hi
                    mma16816(acc[mt][nt], ahi[mt], blo);   // hi*lo
                    mma16816(acc[mt][nt], alo[mt], bhi);   // lo*hi
                }
            }
        }
        __syncthreads();
    }

    // --- epilogue: tanh(acc + bias)*uw, reduce over n ---
    const float* bs  = (const float*)(smem + OFF_BIAS);
    const float* uws = (const float*)(smem + OFF_UW);
    float sR[4] = {0.f, 0.f, 0.f, 0.f};   // rows wm*32 + mt*16 + h*8 + g
#pragma unroll
    for (int mt = 0; mt < 2; mt++)
#pragma unroll
        for (int nt = 0; nt < 8; nt++) {
            int n0 = wn * 64 + nt * 8 + 2 * t;
            float b0 = bs[n0], b1 = bs[n0 + 1];
            float u0 = uws[n0], u1 = uws[n0 + 1];
            sR[mt * 2 + 0] += tanh_approx(acc[mt][nt][0] + b0) * u0
                            + tanh_approx(acc[mt][nt][1] + b1) * u1;
            sR[mt * 2 + 1] += tanh_approx(acc[mt][nt][2] + b0) * u0
                            + tanh_approx(acc[mt][nt][3] + b1) * u1;
        }
    // reduce across the quad (t dimension)
#pragma unroll
    for (int off = 1; off < 4; off <<= 1)
#pragma unroll
        for (int i = 0; i < 4; i++)
            sR[i] += __shfl_xor_sync(0xffffffffu, sR[i], off);

    float* red = (float*)(smem + OFF_RED);
    if (t == 0) {
#pragma unroll
        for (int mt = 0; mt < 2; mt++)
#pragma unroll
            for (int h = 0; h < 2; h++) {
                int row = wm * 32 + mt * 16 + h * 8 + g;
                red[row * 4 + wn] = sR[mt * 2 + h];
            }
    }
    __syncthreads();

    if (tid < MT) {
        float e = red[tid * 4] + red[tid * 4 + 1] + red[tid * 4 + 2] + red[tid * 4 + 3];
        long rg = rowbase + tid;
        g_score[rg] = expf(e) * (float)mask[rg];
    }
}

// ---------------------------------------------------------------------------
// Kernel 2: per-batch denominator
// ---------------------------------------------------------------------------
__global__ void denom_kernel()
{
    __shared__ float red[256];
    const int b = blockIdx.x, tid = threadIdx.x;
    float s = 0.0f;
    for (int t = tid; t < TT; t += 256) s += g_score[(long)b * TT + t];
    red[tid] = s;
    __syncthreads();
    for (int o = 128; o > 0; o >>= 1) {
        if (tid < o) red[tid] += red[tid + o];
        __syncthreads();
    }
    if (tid == 0) g_denom[b] = red[0] + EPSF;
}

// ---------------------------------------------------------------------------
// Kernel 3: split-T weighted sum (deterministic partials)
// ---------------------------------------------------------------------------
__global__ __launch_bounds__(256)
void weighted_kernel(const float* __restrict__ x)
{
    const int b = blockIdx.x, ts = blockIdx.y, d = threadIdx.x;
    __shared__ float sc[TCHUNK];
    const int t0 = ts * TCHUNK;
    if (d < TCHUNK) sc[d] = g_score[(long)b * TT + t0 + d];
    __syncthreads();

    float acc = 0.0f;
    const float* xp = x + ((long)b * TT + t0) * DD + d;
#pragma unroll 4
    for (int t = 0; t < TCHUNK; t++)
        acc = fmaf(xp[(long)t * DD], sc[t], acc);
    g_partial[((long)b * TSPLIT + ts) * DD + d] = acc;
}

// ---------------------------------------------------------------------------
// Kernel 4: finalize
// ---------------------------------------------------------------------------
__global__ void finalize_kernel(float* __restrict__ out)
{
    const int b = blockIdx.x, d = threadIdx.x;
    float s = 0.0f;
#pragma unroll
    for (int ts = 0; ts < TSPLIT; ts++)
        s += g_partial[((long)b * TSPLIT + ts) * DD + d];
    out[b * DD + d] = s / g_denom[b];
}

// ---------------------------------------------------------------------------
extern "C" void kernel_launch(void* const* d_in, const int* in_sizes, int n_in,
                              void* d_out, int out_size)
{
    const float* x    = (const float*)d_in[0];  // [64,2048,256]
    const float* W    = (const float*)d_in[1];  // [256,256]
    const float* bias = (const float*)d_in[2];  // [256]
    const float* uw   = (const float*)d_in[3];  // [256]
    const int*   mask = (const int*)  d_in[4];  // [64,2048]
    float* out = (float*)d_out;                 // [64,256]

    cudaFuncSetAttribute(score_mma_kernel,
                         cudaFuncAttributeMaxDynamicSharedMemorySize, SMEM_BYTES);

    prep_w<<<DD, DD>>>(W);
    score_mma_kernel<<<BT / MT, 256, SMEM_BYTES>>>(x, bias, uw, mask);
    denom_kernel<<<BB, 256>>>();
    weighted_kernel<<<dim3(BB, TSPLIT), 256>>>(x);
    finalize_kernel<<<BB, DD>>>(out);
}

// round 9
// speedup vs baseline: 2.9370x; 1.1748x over previous
#include <cuda_runtime.h>
#include <cuda_bf16.h>
#include <cstdint>
#include <math.h>

#define BB 64
#define TT 2048
#define DD 256
#define BT (BB*TT)
#define EPSF 1e-7f

#define MT 64             // rows per tile
#define NRT (BT/MT)       // 2048 row-tiles
#define GY 74             // persistent CTAs per n-half (2*74 = 148 = one wave)
#define NH 128            // n per half
#define SKX 264           // padded x smem stride (elems)
#define SKW 264           // padded W smem stride (elems)
#define TSPLIT 16
#define TCHUNK (TT/TSPLIT)

// ---------------- scratch ----------------
__device__ __nv_bfloat16 g_Whi[DD*DD];   // W^T hi, [n][k]
__device__ __nv_bfloat16 g_Wlo[DD*DD];   // W^T lo, [n][k]
__device__ float g_epart[2*BT];          // partial e per n-half
__device__ float g_score[BT];
__device__ float g_denom[BB];
__device__ float g_partial[BB*TSPLIT*DD];

// ---------------- smem layout (bytes) ----------------
#define OFF_XHI  0
#define OFF_XLO  (MT*SKX*2)                  // 33792
#define OFF_WHI  (2*MT*SKX*2)                // 67584
#define OFF_WLO  (OFF_WHI + NH*SKW*2)        // 135168
#define OFF_RED  (OFF_WLO + NH*SKW*2)        // 202752
#define OFF_BIAS (OFF_RED + MT*4*4)          // 203776
#define OFF_UW   (OFF_BIAS + NH*4)           // 204288
#define SMEM_BYTES (OFF_UW + NH*4)           // 204800

// ---------------- helpers ----------------
__device__ __forceinline__ void mma16816(float* c, const uint32_t* a, const uint32_t* b) {
    asm volatile(
        "mma.sync.aligned.m16n8k16.row.col.f32.bf16.bf16.f32 "
        "{%0,%1,%2,%3}, {%4,%5,%6,%7}, {%8,%9}, {%0,%1,%2,%3};"
        : "+f"(c[0]), "+f"(c[1]), "+f"(c[2]), "+f"(c[3])
        : "r"(a[0]), "r"(a[1]), "r"(a[2]), "r"(a[3]), "r"(b[0]), "r"(b[1]));
}
__device__ __forceinline__ void ldm_x4(uint32_t* r, uint32_t addr) {
    asm volatile("ldmatrix.sync.aligned.m8n8.x4.shared.b16 {%0,%1,%2,%3}, [%4];"
        : "=r"(r[0]), "=r"(r[1]), "=r"(r[2]), "=r"(r[3]) : "r"(addr));
}
__device__ __forceinline__ float tanh_approx(float x) {
    float y;
    asm("tanh.approx.f32 %0, %1;" : "=f"(y) : "f"(x));
    return y;
}
__device__ __forceinline__ uint32_t smem_to_u32(const void* p) {
    uint32_t a;
    asm("{ .reg .u64 t; cvta.to.shared.u64 t, %1; cvt.u32.u64 %0, t; }"
        : "=r"(a) : "l"(p));
    return a;
}
// split two fp32 into packed bf16x2 hi-word / lo-word
__device__ __forceinline__ void split2(float a, float b, uint32_t& hi, uint32_t& lo) {
    __nv_bfloat16 ha = __float2bfloat16(a), hb = __float2bfloat16(b);
    float la = a - __bfloat162float(ha);
    float lb = b - __bfloat162float(hb);
    __nv_bfloat162 H; H.x = ha; H.y = hb;
    __nv_bfloat162 L; L.x = __float2bfloat16(la); L.y = __float2bfloat16(lb);
    hi = *reinterpret_cast<uint32_t*>(&H);
    lo = *reinterpret_cast<uint32_t*>(&L);
}

// ---------------------------------------------------------------------------
// Kernel 0: pre-split & transpose W -> g_Whi/g_Wlo as [n][k]
// ---------------------------------------------------------------------------
__global__ void prep_w(const float* __restrict__ W) {
    int n = blockIdx.x, k = threadIdx.x;
    float w = W[k * DD + n];
    __nv_bfloat16 h = __float2bfloat16(w);
    g_Whi[n * DD + k] = h;
    g_Wlo[n * DD + k] = __float2bfloat16(w - __bfloat162float(h));
}

// ---------------------------------------------------------------------------
// Kernel 1: persistent split-bf16 mma.sync GEMM, W resident in smem.
// Grid (2 n-halves, 74). 8 warps: wm = wid&1 (M 2x32), wn = wid>>1 (N 4x32).
// Writes partial e (reduction over this CTA's 128 n) to g_epart.
// ---------------------------------------------------------------------------
__global__ __launch_bounds__(256, 1)
void score_mma_kernel(const float* __restrict__ x,
                      const float* __restrict__ bias,
                      const float* __restrict__ uw)
{
    extern __shared__ char smem[];
    const uint32_t sbu = smem_to_u32(smem);
    const int tid = threadIdx.x, wid = tid >> 5, lane = tid & 31;
    const int wm = wid & 1, wn = wid >> 1;
    const int g = lane >> 2, t = lane & 3;
    const int nhalf = blockIdx.x;

    // ---- stage W half (once): thread -> n = tid>>1, k-half = (tid&1)*128 ----
    {
        int n = tid >> 1, kh = (tid & 1) * 128;
        const uint4* wh = (const uint4*)(g_Whi + (size_t)(nhalf * NH + n) * DD + kh);
        const uint4* wl = (const uint4*)(g_Wlo + (size_t)(nhalf * NH + n) * DD + kh);
        char* dh = smem + OFF_WHI + (size_t)(n * SKW + kh) * 2;
        char* dl = smem + OFF_WLO + (size_t)(n * SKW + kh) * 2;
#pragma unroll
        for (int q = 0; q < 16; q++) {
            ((uint4*)dh)[q] = wh[q];
            ((uint4*)dl)[q] = wl[q];
        }
    }
    if (tid < NH) {
        ((float*)(smem + OFF_BIAS))[tid] = bias[nhalf * NH + tid];
        ((float*)(smem + OFF_UW))[tid]   = uw[nhalf * NH + tid];
    }

    // ---- ldmatrix per-lane base addresses ----
    const int rsel = (lane & 7) + ((lane >> 3) & 1) * 8;   // row within 16
    const int ksel = (lane >> 4) * 8;                      // k offset 0/8
    uint32_t aBase[2], bBase[2];
#pragma unroll
    for (int mt = 0; mt < 2; mt++)
        aBase[mt] = sbu + (uint32_t)(((wm * 32 + mt * 16 + rsel) * SKX + ksel) * 2);
#pragma unroll
    for (int gb = 0; gb < 2; gb++)
        bBase[gb] = sbu + OFF_WHI + (uint32_t)(((wn * 32 + gb * 16 + rsel) * SKW + ksel) * 2);

    // ---- x staging map: thread -> row xr, k-quarter xq ----
    const int xr = tid >> 2, xq = (tid & 3) * 64;
    float4 pre[16];
    int rt = blockIdx.y;
    {
        const float4* xp = (const float4*)(x + ((size_t)rt * MT + xr) * DD + xq);
#pragma unroll
        for (int q = 0; q < 16; q++) pre[q] = xp[q];
    }
    __syncthreads();   // W/bias staged

    const float* bs = (const float*)(smem + OFF_BIAS);
    const float* us = (const float*)(smem + OFF_UW);
    float* red = (float*)(smem + OFF_RED);

    for (; rt < NRT; rt += GY) {
        // ---- convert prefetched x -> split bf16 smem ----
#pragma unroll
        for (int q = 0; q < 16; q++) {
            uint32_t h01, l01, h23, l23;
            split2(pre[q].x, pre[q].y, h01, l01);
            split2(pre[q].z, pre[q].w, h23, l23);
            size_t e2 = (size_t)(xr * SKX + xq + q * 4) * 2;
            *(uint2*)(smem + OFF_XHI + e2) = make_uint2(h01, h23);
            *(uint2*)(smem + OFF_XLO + e2) = make_uint2(l01, l23);
        }
        __syncthreads();

        // ---- prefetch next tile (overlaps MMA) ----
        if (rt + GY < NRT) {
            const float4* xp = (const float4*)(x + ((size_t)(rt + GY) * MT + xr) * DD + xq);
#pragma unroll
            for (int q = 0; q < 16; q++) pre[q] = xp[q];
        }

        float acc[2][4][4];
#pragma unroll
        for (int mt = 0; mt < 2; mt++)
#pragma unroll
            for (int nt = 0; nt < 4; nt++)
#pragma unroll
                for (int i = 0; i < 4; i++) acc[mt][nt][i] = 0.0f;

        // ---- 16 k16-steps, full K=256 ----
#pragma unroll
        for (int ks = 0; ks < 16; ks++) {
            const uint32_t kb2 = (uint32_t)ks * 32;   // k offset in bytes
            uint32_t ah[2][4], al[2][4], bh[2][4], bl[2][4];
            ldm_x4(ah[0], aBase[0] + kb2);
            ldm_x4(ah[1], aBase[1] + kb2);
            ldm_x4(al[0], aBase[0] + OFF_XLO + kb2);
            ldm_x4(al[1], aBase[1] + OFF_XLO + kb2);
            ldm_x4(bh[0], bBase[0] + kb2);
            ldm_x4(bh[1], bBase[1] + kb2);
            ldm_x4(bl[0], bBase[0] + (OFF_WLO - OFF_WHI) + kb2);
            ldm_x4(bl[1], bBase[1] + (OFF_WLO - OFF_WHI) + kb2);
#pragma unroll
            for (int nt = 0; nt < 4; nt++) {
                const int gb = nt >> 1, s = nt & 1;
                uint32_t Bh[2] = { bh[gb][s], bh[gb][s + 2] };
                uint32_t Bl[2] = { bl[gb][s], bl[gb][s + 2] };
#pragma unroll
                for (int mt = 0; mt < 2; mt++) {
                    mma16816(acc[mt][nt], ah[mt], Bh);   // hi*hi
                    mma16816(acc[mt][nt], ah[mt], Bl);   // hi*lo
                    mma16816(acc[mt][nt], al[mt], Bh);   // lo*hi
                }
            }
        }

        // ---- epilogue: tanh(acc+bias)*uw, reduce this CTA's 128 n ----
        float sR[4] = {0.f, 0.f, 0.f, 0.f};
#pragma unroll
        for (int mt = 0; mt < 2; mt++)
#pragma unroll
            for (int nt = 0; nt < 4; nt++) {
                int n0 = wn * 32 + nt * 8 + 2 * t;
                float b0 = bs[n0], b1 = bs[n0 + 1];
                float u0 = us[n0], u1 = us[n0 + 1];
                sR[mt * 2 + 0] += tanh_approx(acc[mt][nt][0] + b0) * u0
                                + tanh_approx(acc[mt][nt][1] + b1) * u1;
                sR[mt * 2 + 1] += tanh_approx(acc[mt][nt][2] + b0) * u0
                                + tanh_approx(acc[mt][nt][3] + b1) * u1;
            }
#pragma unroll
        for (int off = 1; off < 4; off <<= 1)
#pragma unroll
            for (int i = 0; i < 4; i++)
                sR[i] += __shfl_xor_sync(0xffffffffu, sR[i], off);

        if (t == 0) {
#pragma unroll
            for (int mt = 0; mt < 2; mt++)
#pragma unroll
                for (int h = 0; h < 2; h++)
                    red[(wm * 32 + mt * 16 + h * 8 + g) * 4 + wn] = sR[mt * 2 + h];
        }
        __syncthreads();
        if (tid < MT) {
            float e = red[tid * 4] + red[tid * 4 + 1] + red[tid * 4 + 2] + red[tid * 4 + 3];
            g_epart[(size_t)nhalf * BT + (size_t)rt * MT + tid] = e;
        }
        // next-iter STS is safe: all frag reads done before the barrier above;
        // red rewritten only after next iteration's post-STS barrier.
    }
}

// ---------------------------------------------------------------------------
// Kernel 2: combine partial e, exp*mask, per-batch denominator
// ---------------------------------------------------------------------------
__global__ void denom_kernel(const int* __restrict__ mask)
{
    __shared__ float redc[256];
    const int b = blockIdx.x, tid = threadIdx.x;
    float s = 0.0f;
    for (int t0 = tid; t0 < TT; t0 += 256) {
        size_t row = (size_t)b * TT + t0;
        float e = g_epart[row] + g_epart[BT + row];
        float sc = expf(e) * (float)mask[row];
        g_score[row] = sc;
        s += sc;
    }
    redc[tid] = s;
    __syncthreads();
    for (int o = 128; o > 0; o >>= 1) {
        if (tid < o) redc[tid] += redc[tid + o];
        __syncthreads();
    }
    if (tid == 0) g_denom[b] = redc[0] + EPSF;
}

// ---------------------------------------------------------------------------
// Kernel 3: split-T weighted sum, float4 loads, 4 independent acc chains
// 256 thr: tsub = tid>>6 (4-way t split), dq = tid&63 (d quad)
// ---------------------------------------------------------------------------
__global__ __launch_bounds__(256)
void weighted_kernel(const float* __restrict__ x)
{
    const int b = blockIdx.x, ts = blockIdx.y, tid = threadIdx.x;
    const int tsub = tid >> 6, dq = tid & 63;
    __shared__ float sc[TCHUNK];
    __shared__ float red[4][DD];
    const int t0 = ts * TCHUNK;
    if (tid < TCHUNK) sc[tid] = g_score[(size_t)b * TT + t0 + tid];
    __syncthreads();

    float a0 = 0.f, a1 = 0.f, a2 = 0.f, a3 = 0.f;
    const float* xb = x + ((size_t)b * TT + t0) * DD;
#pragma unroll 8
    for (int tt = tsub * 32; tt < tsub * 32 + 32; tt++) {
        float4 v = *(const float4*)(xb + (size_t)tt * DD + dq * 4);
        float s = sc[tt];
        a0 = fmaf(v.x, s, a0); a1 = fmaf(v.y, s, a1);
        a2 = fmaf(v.z, s, a2); a3 = fmaf(v.w, s, a3);
    }
    *(float4*)&red[tsub][dq * 4] = make_float4(a0, a1, a2, a3);
    __syncthreads();

    float sum = red[0][tid] + red[1][tid] + red[2][tid] + red[3][tid];
    g_partial[((size_t)b * TSPLIT + ts) * DD + tid] = sum;
}

// ---------------------------------------------------------------------------
// Kernel 4: finalize
// ---------------------------------------------------------------------------
__global__ void finalize_kernel(float* __restrict__ out)
{
    const int b = blockIdx.x, d = threadIdx.x;
    float s = 0.0f;
#pragma unroll
    for (int ts = 0; ts < TSPLIT; ts++)
        s += g_partial[((size_t)b * TSPLIT + ts) * DD + d];
    out[b * DD + d] = s / g_denom[b];
}

// ---------------------------------------------------------------------------
extern "C" void kernel_launch(void* const* d_in, const int* in_sizes, int n_in,
                              void* d_out, int out_size)
{
    const float* x    = (const float*)d_in[0];  // [64,2048,256]
    const float* W    = (const float*)d_in[1];  // [256,256]
    const float* bias = (const float*)d_in[2];  // [256]
    const float* uw   = (const float*)d_in[3];  // [256]
    const int*   mask = (const int*)  d_in[4];  // [64,2048]
    float* out = (float*)d_out;                 // [64,256]

    cudaFuncSetAttribute(score_mma_kernel,
                         cudaFuncAttributeMaxDynamicSharedMemorySize, SMEM_BYTES);

    prep_w<<<DD, DD>>>(W);
    score_mma_kernel<<<dim3(2, GY), 256, SMEM_BYTES>>>(x, bias, uw);
    denom_kernel<<<BB, 256>>>(mask);
    weighted_kernel<<<dim3(BB, TSPLIT), 256>>>(x);
    finalize_kernel<<<BB, DD>>>(out);
}

// round 11
// speedup vs baseline: 5.1639x; 1.7582x over previous
#include <cuda_runtime.h>
#include <cuda_fp16.h>
#include <cstdint>
#include <math.h>

#define BB 64
#define TT 2048
#define DD 256
#define BT (BB*TT)
#define EPSF 1e-7f

#define MT 64             // rows per tile
#define NRT (BT/MT)       // 2048 row-tiles
#define NCTA 148          // persistent CTAs = one full wave
#define SK 264            // padded smem stride (fp16 elems)
#define TSPLIT 16
#define TCHUNK (TT/TSPLIT)

// ---------------- scratch ----------------
__device__ __half g_Wh[DD*DD];           // W^T fp16, [n][k]
__device__ float g_score[BT];
__device__ float g_denom[BB];
__device__ float g_partial[BB*TSPLIT*DD];

// ---------------- smem layout (bytes) ----------------
#define OFF_X0   0
#define OFF_X1   (MT*SK*2)                 // 33792
#define OFF_W    (2*MT*SK*2)               // 67584
#define OFF_RED  (OFF_W + DD*SK*2)         // 202752 : red[64][4]
#define OFF_BIAS (OFF_RED + MT*4*4)        // 203776
#define OFF_UW   (OFF_BIAS + DD*4)         // 204800
#define SMEM_BYTES (OFF_UW + DD*4)         // 205824

// ---------------- helpers ----------------
__device__ __forceinline__ void mma16816h(float* c, const uint32_t* a, const uint32_t* b) {
    asm volatile(
        "mma.sync.aligned.m16n8k16.row.col.f32.f16.f16.f32 "
        "{%0,%1,%2,%3}, {%4,%5,%6,%7}, {%8,%9}, {%0,%1,%2,%3};"
        : "+f"(c[0]), "+f"(c[1]), "+f"(c[2]), "+f"(c[3])
        : "r"(a[0]), "r"(a[1]), "r"(a[2]), "r"(a[3]), "r"(b[0]), "r"(b[1]));
}
__device__ __forceinline__ void ldm_x4(uint32_t* r, uint32_t addr) {
    asm volatile("ldmatrix.sync.aligned.m8n8.x4.shared.b16 {%0,%1,%2,%3}, [%4];"
        : "=r"(r[0]), "=r"(r[1]), "=r"(r[2]), "=r"(r[3]) : "r"(addr));
}
__device__ __forceinline__ float tanh_approx(float x) {
    float y;
    asm("tanh.approx.f32 %0, %1;" : "=f"(y) : "f"(x));
    return y;
}
__device__ __forceinline__ uint32_t smem_to_u32(const void* p) {
    uint32_t a;
    asm("{ .reg .u64 t; cvta.to.shared.u64 t, %1; cvt.u32.u64 %0, t; }"
        : "=r"(a) : "l"(p));
    return a;
}
__device__ __forceinline__ uint2 cvt4(float4 v) {
    __half2 h01 = __floats2half2_rn(v.x, v.y);
    __half2 h23 = __floats2half2_rn(v.z, v.w);
    return make_uint2(*reinterpret_cast<uint32_t*>(&h01),
                      *reinterpret_cast<uint32_t*>(&h23));
}

// ---------------------------------------------------------------------------
// Kernel 0: W -> fp16 W^T [n][k]
// ---------------------------------------------------------------------------
__global__ void prep_w(const float* __restrict__ W) {
    int n = blockIdx.x, k = threadIdx.x;
    g_Wh[n * DD + k] = __float2half(W[k * DD + n]);
}

// ---------------------------------------------------------------------------
// Kernel 1: persistent fp16 mma.sync GEMM, full W (N=256) resident in smem,
// double-buffered x tiles. Grid 148. 8 warps: wm = wid&1 (M 2x32),
// wn = wid>>1 (N 4x64). Writes exp(e)*mask directly to g_score.
// ---------------------------------------------------------------------------
__global__ __launch_bounds__(256, 1)
void score_mma_kernel(const float* __restrict__ x,
                      const float* __restrict__ bias,
                      const float* __restrict__ uw,
                      const int*   __restrict__ mask)
{
    extern __shared__ char smem[];
    const uint32_t sbu = smem_to_u32(smem);
    const int tid = threadIdx.x, wid = tid >> 5, lane = tid & 31;
    const int wm = wid & 1, wn = wid >> 1;
    const int g = lane >> 2, t = lane & 3;

    // ---- stage full W^T (once): thread -> n = tid, all 256 k ----
    {
        const uint4* wp = (const uint4*)(g_Wh + (size_t)tid * DD);
        char* dst = smem + OFF_W + (size_t)tid * SK * 2;
#pragma unroll
        for (int q = 0; q < 32; q++) ((uint4*)dst)[q] = wp[q];
    }
    ((float*)(smem + OFF_BIAS))[tid] = bias[tid];
    ((float*)(smem + OFF_UW))[tid]   = uw[tid];

    // ---- first tile: fp32 -> fp16 convert into buf0 ----
    const int xr = tid >> 2, xq = (tid & 3) * 64;
    int rt = blockIdx.x;
    {
        const float4* xp = (const float4*)(x + ((size_t)rt * MT + xr) * DD + xq);
        char* db = smem + OFF_X0 + (size_t)(xr * SK + xq) * 2;
#pragma unroll
        for (int q = 0; q < 16; q++)
            *(uint2*)(db + q * 8) = cvt4(xp[q]);
    }
    __syncthreads();

    // ---- ldmatrix per-lane addressing ----
    const int rsel = (lane & 7) + ((lane >> 3) & 1) * 8;
    const int ksel = (lane >> 4) * 8;
    uint32_t aOff[2], bBase[4];
#pragma unroll
    for (int mt = 0; mt < 2; mt++)
        aOff[mt] = (uint32_t)(((wm * 32 + mt * 16 + rsel) * SK + ksel) * 2);
#pragma unroll
    for (int gb = 0; gb < 4; gb++)
        bBase[gb] = sbu + OFF_W + (uint32_t)(((wn * 64 + gb * 16 + rsel) * SK + ksel) * 2);

    const float* bs = (const float*)(smem + OFF_BIAS);
    const float* us = (const float*)(smem + OFF_UW);
    float* red = (float*)(smem + OFF_RED);

    uint32_t bufo = OFF_X0;
    for (; rt < NRT; rt += NCTA) {
        const bool hasnext = (rt + NCTA < NRT);

        // ---- prefetch next tile into regs (overlaps MMA) ----
        float4 pre[16];
        if (hasnext) {
            const float4* xp = (const float4*)(x + ((size_t)(rt + NCTA) * MT + xr) * DD + xq);
#pragma unroll
            for (int q = 0; q < 16; q++) pre[q] = xp[q];
        }

        float acc[2][8][4];
#pragma unroll
        for (int mt = 0; mt < 2; mt++)
#pragma unroll
            for (int nt = 0; nt < 8; nt++)
#pragma unroll
                for (int i = 0; i < 4; i++) acc[mt][nt][i] = 0.0f;

        const uint32_t aBase0 = sbu + bufo + aOff[0];
        const uint32_t aBase1 = sbu + bufo + aOff[1];

        // ---- 16 k16-steps, full K=256, single fp16 term ----
#pragma unroll
        for (int ks = 0; ks < 16; ks++) {
            const uint32_t kb2 = (uint32_t)ks * 32;
            uint32_t a0[4], a1[4], b[4][4];
            ldm_x4(a0, aBase0 + kb2);
            ldm_x4(a1, aBase1 + kb2);
#pragma unroll
            for (int gb = 0; gb < 4; gb++) ldm_x4(b[gb], bBase[gb] + kb2);
#pragma unroll
            for (int nt = 0; nt < 8; nt++) {
                const int gb = nt >> 1, s = nt & 1;
                uint32_t B[2] = { b[gb][s], b[gb][s + 2] };
                mma16816h(acc[0][nt], a0, B);
                mma16816h(acc[1][nt], a1, B);
            }
        }

        // ---- convert prefetched tile into the other buffer (no barrier needed:
        //      writes target nbuf, MMA above read bufo) ----
        const uint32_t nbufo = (bufo == OFF_X0) ? OFF_X1 : OFF_X0;
        if (hasnext) {
            char* db = smem + nbufo + (size_t)(xr * SK + xq) * 2;
#pragma unroll
            for (int q = 0; q < 16; q++)
                *(uint2*)(db + q * 8) = cvt4(pre[q]);
        }

        // ---- epilogue: tanh(acc+bias)*uw, full 256-n reduction ----
        float sR[4] = {0.f, 0.f, 0.f, 0.f};
#pragma unroll
        for (int mt = 0; mt < 2; mt++)
#pragma unroll
            for (int nt = 0; nt < 8; nt++) {
                int n0 = wn * 64 + nt * 8 + 2 * t;
                float b0 = bs[n0], b1 = bs[n0 + 1];
                float u0 = us[n0], u1 = us[n0 + 1];
                sR[mt * 2 + 0] += tanh_approx(acc[mt][nt][0] + b0) * u0
                                + tanh_approx(acc[mt][nt][1] + b1) * u1;
                sR[mt * 2 + 1] += tanh_approx(acc[mt][nt][2] + b0) * u0
                                + tanh_approx(acc[mt][nt][3] + b1) * u1;
            }
#pragma unroll
        for (int off = 1; off < 4; off <<= 1)
#pragma unroll
            for (int i = 0; i < 4; i++)
                sR[i] += __shfl_xor_sync(0xffffffffu, sR[i], off);

        if (t == 0) {
#pragma unroll
            for (int mt = 0; mt < 2; mt++)
#pragma unroll
                for (int h = 0; h < 2; h++)
                    red[(wm * 32 + mt * 16 + h * 8 + g) * 4 + wn] = sR[mt * 2 + h];
        }
        __syncthreads();
        if (tid < MT) {
            float e = red[tid * 4] + red[tid * 4 + 1] + red[tid * 4 + 2] + red[tid * 4 + 3];
            size_t row = (size_t)rt * MT + tid;
            g_score[row] = expf(e) * (float)mask[row];
        }
        __syncthreads();   // protect red[] and buffer swap across iterations
        bufo = nbufo;
    }
}

// ---------------------------------------------------------------------------
// Kernel 2: per-batch denominator
// ---------------------------------------------------------------------------
__global__ void denom_kernel()
{
    __shared__ float redc[256];
    const int b = blockIdx.x, tid = threadIdx.x;
    float s = 0.0f;
    for (int t0 = tid; t0 < TT; t0 += 256)
        s += g_score[(size_t)b * TT + t0];
    redc[tid] = s;
    __syncthreads();
    for (int o = 128; o > 0; o >>= 1) {
        if (tid < o) redc[tid] += redc[tid + o];
        __syncthreads();
    }
    if (tid == 0) g_denom[b] = redc[0] + EPSF;
}

// ---------------------------------------------------------------------------
// Kernel 3: split-T weighted sum, float4 loads, 4 independent acc chains
// ---------------------------------------------------------------------------
__global__ __launch_bounds__(256)
void weighted_kernel(const float* __restrict__ x)
{
    const int b = blockIdx.x, ts = blockIdx.y, tid = threadIdx.x;
    const int tsub = tid >> 6, dq = tid & 63;
    __shared__ float sc[TCHUNK];
    __shared__ float red[4][DD];
    const int t0 = ts * TCHUNK;
    if (tid < TCHUNK) sc[tid] = g_score[(size_t)b * TT + t0 + tid];
    __syncthreads();

    float a0 = 0.f, a1 = 0.f, a2 = 0.f, a3 = 0.f;
    const float* xb = x + ((size_t)b * TT + t0) * DD;
#pragma unroll 8
    for (int tt = tsub * 32; tt < tsub * 32 + 32; tt++) {
        float4 v = *(const float4*)(xb + (size_t)tt * DD + dq * 4);
        float s = sc[tt];
        a0 = fmaf(v.x, s, a0); a1 = fmaf(v.y, s, a1);
        a2 = fmaf(v.z, s, a2); a3 = fmaf(v.w, s, a3);
    }
    *(float4*)&red[tsub][dq * 4] = make_float4(a0, a1, a2, a3);
    __syncthreads();

    float sum = red[0][tid] + red[1][tid] + red[2][tid] + red[3][tid];
    g_partial[((size_t)b * TSPLIT + ts) * DD + tid] = sum;
}

// ---------------------------------------------------------------------------
// Kernel 4: finalize
// ---------------------------------------------------------------------------
__global__ void finalize_kernel(float* __restrict__ out)
{
    const int b = blockIdx.x, d = threadIdx.x;
    float s = 0.0f;
#pragma unroll
    for (int ts = 0; ts < TSPLIT; ts++)
        s += g_partial[((size_t)b * TSPLIT + ts) * DD + d];
    out[b * DD + d] = s / g_denom[b];
}

// ---------------------------------------------------------------------------
extern "C" void kernel_launch(void* const* d_in, const int* in_sizes, int n_in,
                              void* d_out, int out_size)
{
    const float* x    = (const float*)d_in[0];  // [64,2048,256]
    const float* W    = (const float*)d_in[1];  // [256,256]
    const float* bias = (const float*)d_in[2];  // [256]
    const float* uw   = (const float*)d_in[3];  // [256]
    const int*   mask = (const int*)  d_in[4];  // [64,2048]
    float* out = (float*)d_out;                 // [64,256]

    cudaFuncSetAttribute(score_mma_kernel,
                         cudaFuncAttributeMaxDynamicSharedMemorySize, SMEM_BYTES);

    prep_w<<<DD, DD>>>(W);
    score_mma_kernel<<<NCTA, 256, SMEM_BYTES>>>(x, bias, uw, mask);
    denom_kernel<<<BB, 256>>>();
    weighted_kernel<<<dim3(BB, TSPLIT), 256>>>(x);
    finalize_kernel<<<BB, DD>>>(out);
}

// round 17
// speedup vs baseline: 6.0283x; 1.1674x over previous
#include <cuda_runtime.h>
#include <cuda_fp16.h>
#include <cstdint>
#include <math.h>

#define BB 64
#define TT 2048
#define DD 256
#define BT (BB*TT)
#define EPSF 1e-7f

#define MT 64             // rows per tile
#define NRT (BT/MT)       // 2048 row-tiles
#define TPB 32            // tiles per batch
#define NCTA 148          // persistent CTAs = one full wave
#define SK 264            // padded smem stride (fp16 elems)

// ---------------- scratch ----------------
__device__ __half g_Wh[DD*DD];           // W^T fp16, [n][k]
__device__ float g_tilesum[NRT*DD];      // per-tile weighted x sums
__device__ float g_scsum[NRT];           // per-tile score sums

// ---------------- smem layout (bytes) ----------------
#define OFF_X0   0
#define OFF_X1   (MT*SK*2)                 // 33792
#define OFF_W    (2*MT*SK*2)               // 67584
#define OFF_RED  (OFF_W + DD*SK*2)         // 202752 : red[64][4]
#define OFF_BIAS (OFF_RED + MT*4*4)        // 203776
#define OFF_UW   (OFF_BIAS + DD*4)         // 204800
#define OFF_SC   (OFF_UW + DD*4)           // 205824 : sc_s[64]
#define OFF_RSC  (OFF_SC + MT*4)           // 206080 : redsc[2]
#define OFF_WS   (OFF_RSC + 8)             // 206088 : wsum[2][256]
#define SMEM_BYTES (OFF_WS + 2*DD*4)       // 208136

// ---------------- helpers ----------------
__device__ __forceinline__ void mma16816h(float* c, const uint32_t* a, const uint32_t* b) {
    asm volatile(
        "mma.sync.aligned.m16n8k16.row.col.f32.f16.f16.f32 "
        "{%0,%1,%2,%3}, {%4,%5,%6,%7}, {%8,%9}, {%0,%1,%2,%3};"
        : "+f"(c[0]), "+f"(c[1]), "+f"(c[2]), "+f"(c[3])
        : "r"(a[0]), "r"(a[1]), "r"(a[2]), "r"(a[3]), "r"(b[0]), "r"(b[1]));
}
__device__ __forceinline__ void ldm_x4(uint32_t* r, uint32_t addr) {
    asm volatile("ldmatrix.sync.aligned.m8n8.x4.shared.b16 {%0,%1,%2,%3}, [%4];"
        : "=r"(r[0]), "=r"(r[1]), "=r"(r[2]), "=r"(r[3]) : "r"(addr));
}
__device__ __forceinline__ float tanh_approx(float x) {
    float y;
    asm("tanh.approx.f32 %0, %1;" : "=f"(y) : "f"(x));
    return y;
}
__device__ __forceinline__ uint32_t smem_to_u32(const void* p) {
    uint32_t a;
    asm("{ .reg .u64 t; cvta.to.shared.u64 t, %1; cvt.u32.u64 %0, t; }"
        : "=r"(a) : "l"(p));
    return a;
}
__device__ __forceinline__ uint2 cvt4(float4 v) {
    __half2 h01 = __floats2half2_rn(v.x, v.y);
    __half2 h23 = __floats2half2_rn(v.z, v.w);
    return make_uint2(*reinterpret_cast<uint32_t*>(&h01),
                      *reinterpret_cast<uint32_t*>(&h23));
}

// ---------------------------------------------------------------------------
// Kernel 0: W -> fp16 W^T [n][k]
// ---------------------------------------------------------------------------
__global__ void prep_w(const float* __restrict__ W) {
    int n = blockIdx.x, k = threadIdx.x;
    g_Wh[n * DD + k] = __float2half(W[k * DD + n]);
}

// ---------------------------------------------------------------------------
// Kernel 1: persistent fp16 mma.sync GEMM, W resident, double-buffered x.
// Fused: per-tile scores AND per-tile weighted x-sums (x already on-chip).
// Grid 148. 8 warps: wm = wid&1 (M 2x32), wn = wid>>1 (N 4x64).
// ---------------------------------------------------------------------------
__global__ __launch_bounds__(256, 1)
void score_mma_kernel(const float* __restrict__ x,
                      const float* __restrict__ bias,
                      const float* __restrict__ uw,
                      const int*   __restrict__ mask)
{
    extern __shared__ char smem[];
    const uint32_t sbu = smem_to_u32(smem);
    const int tid = threadIdx.x, wid = tid >> 5, lane = tid & 31;
    const int wm = wid & 1, wn = wid >> 1;
    const int g = lane >> 2, t = lane & 3;

    // ---- stage full W^T (once) ----
    {
        const uint4* wp = (const uint4*)(g_Wh + (size_t)tid * DD);
        char* dst = smem + OFF_W + (size_t)tid * SK * 2;
#pragma unroll
        for (int q = 0; q < 32; q++) ((uint4*)dst)[q] = wp[q];
    }
    ((float*)(smem + OFF_BIAS))[tid] = bias[tid];
    ((float*)(smem + OFF_UW))[tid]   = uw[tid];

    // ---- first tile: fp32 -> fp16 into buf0 ----
    const int xr = tid >> 2, xq = (tid & 3) * 64;
    int rt = blockIdx.x;
    {
        const float4* xp = (const float4*)(x + ((size_t)rt * MT + xr) * DD + xq);
        char* db = smem + OFF_X0 + (size_t)(xr * SK + xq) * 2;
#pragma unroll
        for (int q = 0; q < 16; q++)
            *(uint2*)(db + q * 8) = cvt4(xp[q]);
    }
    __syncthreads();

    // ---- ldmatrix per-lane addressing ----
    const int rsel = (lane & 7) + ((lane >> 3) & 1) * 8;
    const int ksel = (lane >> 4) * 8;
    uint32_t aOff[2], bBase[4];
#pragma unroll
    for (int mt = 0; mt < 2; mt++)
        aOff[mt] = (uint32_t)(((wm * 32 + mt * 16 + rsel) * SK + ksel) * 2);
#pragma unroll
    for (int gb = 0; gb < 4; gb++)
        bBase[gb] = sbu + OFF_W + (uint32_t)(((wn * 64 + gb * 16 + rsel) * SK + ksel) * 2);

    const float* bs = (const float*)(smem + OFF_BIAS);
    const float* us = (const float*)(smem + OFF_UW);
    float* red   = (float*)(smem + OFF_RED);
    float* sc_s  = (float*)(smem + OFF_SC);
    float* redsc = (float*)(smem + OFF_RSC);
    float* wsum  = (float*)(smem + OFF_WS);   // [2][256]

    uint32_t bufo = OFF_X0;
    for (; rt < NRT; rt += NCTA) {
        const bool hasnext = (rt + NCTA < NRT);

        // ---- prefetch next tile into regs (overlaps MMA) ----
        float4 pre[16];
        if (hasnext) {
            const float4* xp = (const float4*)(x + ((size_t)(rt + NCTA) * MT + xr) * DD + xq);
#pragma unroll
            for (int q = 0; q < 16; q++) pre[q] = xp[q];
        }

        float acc[2][8][4];
#pragma unroll
        for (int mt = 0; mt < 2; mt++)
#pragma unroll
            for (int nt = 0; nt < 8; nt++)
#pragma unroll
                for (int i = 0; i < 4; i++) acc[mt][nt][i] = 0.0f;

        const uint32_t aBase0 = sbu + bufo + aOff[0];
        const uint32_t aBase1 = sbu + bufo + aOff[1];

        // ---- 16 k16-steps, full K=256 ----
#pragma unroll
        for (int ks = 0; ks < 16; ks++) {
            const uint32_t kb2 = (uint32_t)ks * 32;
            uint32_t a0[4], a1[4], b[4][4];
            ldm_x4(a0, aBase0 + kb2);
            ldm_x4(a1, aBase1 + kb2);
#pragma unroll
            for (int gb = 0; gb < 4; gb++) ldm_x4(b[gb], bBase[gb] + kb2);
#pragma unroll
            for (int nt = 0; nt < 8; nt++) {
                const int gb = nt >> 1, s = nt & 1;
                uint32_t B[2] = { b[gb][s], b[gb][s + 2] };
                mma16816h(acc[0][nt], a0, B);
                mma16816h(acc[1][nt], a1, B);
            }
        }

        // ---- convert prefetched tile into the other buffer ----
        const uint32_t nbufo = (bufo == OFF_X0) ? OFF_X1 : OFF_X0;
        if (hasnext) {
            char* db = smem + nbufo + (size_t)(xr * SK + xq) * 2;
#pragma unroll
            for (int q = 0; q < 16; q++)
                *(uint2*)(db + q * 8) = cvt4(pre[q]);
        }

        // ---- epilogue: tanh(acc+bias)*uw, 256-n reduction ----
        float sR[4] = {0.f, 0.f, 0.f, 0.f};
#pragma unroll
        for (int mt = 0; mt < 2; mt++)
#pragma unroll
            for (int nt = 0; nt < 8; nt++) {
                int n0 = wn * 64 + nt * 8 + 2 * t;
                float b0 = bs[n0], b1 = bs[n0 + 1];
                float u0 = us[n0], u1 = us[n0 + 1];
                sR[mt * 2 + 0] += tanh_approx(acc[mt][nt][0] + b0) * u0
                                + tanh_approx(acc[mt][nt][1] + b1) * u1;
                sR[mt * 2 + 1] += tanh_approx(acc[mt][nt][2] + b0) * u0
                                + tanh_approx(acc[mt][nt][3] + b1) * u1;
            }
#pragma unroll
        for (int off = 1; off < 4; off <<= 1)
#pragma unroll
            for (int i = 0; i < 4; i++)
                sR[i] += __shfl_xor_sync(0xffffffffu, sR[i], off);

        if (t == 0) {
#pragma unroll
            for (int mt = 0; mt < 2; mt++)
#pragma unroll
                for (int h = 0; h < 2; h++)
                    red[(wm * 32 + mt * 16 + h * 8 + g) * 4 + wn] = sR[mt * 2 + h];
        }
        __syncthreads();   // (A) red ready

        if (tid < MT) {
            float e = red[tid * 4] + red[tid * 4 + 1] + red[tid * 4 + 2] + red[tid * 4 + 3];
            size_t row = (size_t)rt * MT + tid;
            float sc = expf(e) * (float)mask[row];
            sc_s[tid] = sc;
            float ss = sc;
#pragma unroll
            for (int off = 16; off > 0; off >>= 1)
                ss += __shfl_xor_sync(0xffffffffu, ss, off);
            if ((tid & 31) == 0) redsc[tid >> 5] = ss;
        }
        __syncthreads();   // (B) sc_s / redsc ready

        if (tid == 0) g_scsum[rt] = redsc[0] + redsc[1];

        // ---- fused weighted partial: ytile[d] = sum_rows sc[r]*x16[r][d] ----
        {
            const int half = tid >> 7, dp = tid & 127;
            const char* xb = smem + bufo;
            float wx = 0.f, wy = 0.f;
#pragma unroll 8
            for (int r = half * 32; r < half * 32 + 32; r++) {
                uint32_t h2 = *(const uint32_t*)(xb + (size_t)(r * SK + dp * 2) * 2);
                float2 xv = __half22float2(*reinterpret_cast<const __half2*>(&h2));
                float s = sc_s[r];
                wx = fmaf(xv.x, s, wx);
                wy = fmaf(xv.y, s, wy);
            }
            wsum[half * DD + dp * 2]     = wx;
            wsum[half * DD + dp * 2 + 1] = wy;
        }
        __syncthreads();   // (C) wsum ready

        g_tilesum[(size_t)rt * DD + tid] = wsum[tid] + wsum[DD + tid];
        __syncthreads();   // (D) bufo reads done; red/sc_s/wsum reusable

        bufo = nbufo;
    }
}

// ---------------------------------------------------------------------------
// Kernel 2: finalize — reduce 32 tiles per batch, divide by denominator
// ---------------------------------------------------------------------------
__global__ void finalize_kernel(float* __restrict__ out)
{
    const int b = blockIdx.x, d = threadIdx.x;
    float den = EPSF;
#pragma unroll
    for (int ts = 0; ts < TPB; ts++)
        den += g_scsum[b * TPB + ts];
    float s = 0.0f;
#pragma unroll
    for (int ts = 0; ts < TPB; ts++)
        s += g_tilesum[(size_t)(b * TPB + ts) * DD + d];
    out[b * DD + d] = s / den;
}

// ---------------------------------------------------------------------------
extern "C" void kernel_launch(void* const* d_in, const int* in_sizes, int n_in,
                              void* d_out, int out_size)
{
    const float* x    = (const float*)d_in[0];  // [64,2048,256]
    const float* W    = (const float*)d_in[1];  // [256,256]
    const float* bias = (const float*)d_in[2];  // [256]
    const float* uw   = (const float*)d_in[3];  // [256]
    const int*   mask = (const int*)  d_in[4];  // [64,2048]
    float* out = (float*)d_out;                 // [64,256]

    cudaFuncSetAttribute(score_mma_kernel,
                         cudaFuncAttributeMaxDynamicSharedMemorySize, SMEM_BYTES);

    prep_w<<<DD, DD>>>(W);
    score_mma_kernel<<<NCTA, 256, SMEM_BYTES>>>(x, bias, uw, mask);
    finalize_kernel<<<BB, DD>>>(out);
}